// round 4
// baseline (speedup 1.0000x reference)
#include <cuda_runtime.h>
#include <cuda_bf16.h>
#include <math.h>

#define BB 4
#define LL 2048
#define DD 512
#define KTOP 7
typedef unsigned long long ULL;

// ---------------- scratch (device globals; no allocation allowed) ----------
__device__ float g_part[BB * 16 * DD];
__device__ float g_r[BB * DD];
__device__ float g_mc[BB * LL];
__device__ float g_wt[BB * 8];
__device__ int   g_dl[BB * 8];
__device__ float g_W[DD * DD];
__device__ float g_vagg[(size_t)BB * LL * DD];

// ---------------- packed f32x2 helpers --------------------------------------
__device__ __forceinline__ ULL pack2(float x) {
    ULL r; unsigned u = __float_as_uint(x);
    asm("mov.b64 %0, {%1, %1};" : "=l"(r) : "r"(u));
    return r;
}
__device__ __forceinline__ void fma2(ULL& d, ULL a, ULL b) {
    asm("fma.rn.f32x2 %0, %1, %2, %0;" : "+l"(d) : "l"(a), "l"(b));
}
__device__ __forceinline__ float2 unpack2(ULL v) {
    float2 f;
    asm("mov.b64 {%0, %1}, %2;" : "=f"(f.x), "=f"(f.y) : "l"(v));
    return f;
}

// ---------------- K1: partial column-sums of queries ------------------------
__global__ void k_qpart(const float* __restrict__ q) {
    int b = blockIdx.x, dchunk = blockIdx.y, ts = blockIdx.z;
    int d = dchunk * 256 + threadIdx.x;
    const float* base = q + (size_t)b * LL * DD + (size_t)(ts * 128) * DD + d;
    float s = 0.f;
#pragma unroll 8
    for (int t = 0; t < 128; ++t) s += base[(size_t)t * DD];
    g_part[(b * 16 + ts) * DD + d] = s;
}

// ---------------- K2: r[b] = wk @ (qbar @ wq) * 1/16384 ---------------------
__global__ void k_rvec(const float* __restrict__ wq, const float* __restrict__ wk) {
    __shared__ float qb[DD];
    __shared__ float qs[DD];
    int b = blockIdx.x, tid = threadIdx.x;
    float s = 0.f;
#pragma unroll
    for (int p = 0; p < 16; ++p) s += g_part[(b * 16 + p) * DD + tid];
    qb[tid] = s;
    __syncthreads();
    float acc = 0.f;
    for (int c = 0; c < DD; ++c) acc += qb[c] * wq[(size_t)c * DD + tid];
    qs[tid] = acc;
    __syncthreads();
    const float4* wkr = (const float4*)(wk + (size_t)tid * DD);
    float r = 0.f;
#pragma unroll 4
    for (int d4 = 0; d4 < DD / 4; ++d4) {
        float4 v = wkr[d4];
        r += v.x * qs[d4 * 4] + v.y * qs[d4 * 4 + 1] + v.z * qs[d4 * 4 + 2] + v.w * qs[d4 * 4 + 3];
    }
    g_r[b * DD + tid] = r * (1.0f / (8.0f * 2048.0f));
}

// ---------------- K3: mean_corr[b,j] = keys[b,j,:] . r[b] -------------------
__global__ void k_mc(const float* __restrict__ keys) {
    __shared__ float rs[DD];
    int b = blockIdx.y, tid = threadIdx.x;
    rs[tid] = g_r[b * DD + tid];
    rs[tid + 256] = g_r[b * DD + tid + 256];
    __syncthreads();
    int warp = tid >> 5, lane = tid & 31;
    int j = blockIdx.x * 8 + warp;
    const float* kr = keys + ((size_t)b * LL + j) * DD;
    float acc = 0.f;
#pragma unroll
    for (int i = 0; i < 16; ++i) acc += kr[lane + 32 * i] * rs[lane + 32 * i];
#pragma unroll
    for (int o = 16; o; o >>= 1) acc += __shfl_down_sync(0xffffffffu, acc, o);
    if (lane == 0) g_mc[b * LL + j] = acc;
}

// ---------------- K4: top-7 + softmax, log-merge version --------------------
// grid B, block 256. Thread-local sorted top-7 over 8 strided elems, then an
// 8-level pairwise merge tree in shared (two-pointer merge of sorted lists).
__device__ __forceinline__ bool topgt(float a, int ia, float b, int ib) {
    return a > b || (a == b && ia < ib);  // lax.top_k tie-break: lower index
}
__global__ void k_topk() {
    int b = blockIdx.x, tid = threadIdx.x;
    __shared__ float sv[256][8];
    __shared__ int   si[256][8];
    float v[KTOP]; int ix[KTOP];
#pragma unroll
    for (int j = 0; j < KTOP; ++j) { v[j] = -INFINITY; ix[j] = 0x7fffffff; }
    const float* mc = g_mc + b * LL;
#pragma unroll
    for (int it = 0; it < LL / 256; ++it) {
        int i = tid + it * 256;
        float x = mc[i];
        if (topgt(x, i, v[KTOP - 1], ix[KTOP - 1])) {
            float cv = x; int ci = i;
#pragma unroll
            for (int j = 0; j < KTOP; ++j) {
                if (topgt(cv, ci, v[j], ix[j])) {
                    float tv = v[j]; int ti = ix[j];
                    v[j] = cv; ix[j] = ci;
                    cv = tv; ci = ti;
                }
            }
        }
    }
#pragma unroll
    for (int j = 0; j < KTOP; ++j) { sv[tid][j] = v[j]; si[tid][j] = ix[j]; }
    __syncthreads();
    for (int s = 128; s >= 1; s >>= 1) {
        if (tid < s) {
            float mv[KTOP]; int mi[KTOP];
            int p = 0, q = 0;
#pragma unroll
            for (int r = 0; r < KTOP; ++r) {
                float av = sv[tid][p], bv2 = sv[tid + s][q];
                int   ai = si[tid][p], bi2 = si[tid + s][q];
                if (topgt(av, ai, bv2, bi2)) { mv[r] = av; mi[r] = ai; ++p; }
                else                          { mv[r] = bv2; mi[r] = bi2; ++q; }
            }
#pragma unroll
            for (int r = 0; r < KTOP; ++r) { sv[tid][r] = mv[r]; si[tid][r] = mi[r]; }
        }
        __syncthreads();
    }
    if (tid == 0) {
        float m = sv[0][0];
        float e[KTOP], ssum = 0.f;
#pragma unroll
        for (int i = 0; i < KTOP; ++i) { e[i] = expf(sv[0][i] - m); ssum += e[i]; }
        float inv = 1.0f / ssum;
#pragma unroll
        for (int i = 0; i < KTOP; ++i) { g_wt[b * 8 + i] = e[i] * inv; g_dl[b * 8 + i] = si[0][i]; }
    }
}

// ---------------- main GEMM: out = g_vagg @ g_W, f32x2, 128x128x32 ----------
// 256 threads, 8x8 per thread (as 8 rows x 4 f32x2 col-pairs)
__global__ __launch_bounds__(256, 2) void k_gemm_main(float* __restrict__ out) {
    __shared__ float As[32][132];   // padded: 132*4=528B row, 16B-aligned
    __shared__ float Bs[32][128];
    const float* A = g_vagg;
    const float* B = g_W;
    int tid = threadIdx.x;
    int tx = tid & 15, ty = tid >> 4;
    int rowBase = blockIdx.y * 128, colBase = blockIdx.x * 128;
    ULL acc[8][4];
#pragma unroll
    for (int i = 0; i < 8; ++i)
#pragma unroll
        for (int j = 0; j < 4; ++j) acc[i][j] = 0ull;

    for (int k0 = 0; k0 < DD; k0 += 32) {
#pragma unroll
        for (int i = 0; i < 4; ++i) {
            int idx = tid + i * 256;
            int r = idx >> 3;           // 0..127
            int c4 = (idx & 7) * 4;     // 0..28
            float4 v = *(const float4*)(A + (size_t)(rowBase + r) * DD + k0 + c4);
            As[c4][r] = v.x; As[c4 + 1][r] = v.y; As[c4 + 2][r] = v.z; As[c4 + 3][r] = v.w;
        }
#pragma unroll
        for (int i = 0; i < 4; ++i) {
            int idx = tid + i * 256;
            int r = idx >> 5;           // 0..31
            int c4 = (idx & 31) * 4;    // 0..124
            *(float4*)&Bs[r][c4] = *(const float4*)(B + (size_t)(k0 + r) * DD + colBase + c4);
        }
        __syncthreads();
#pragma unroll 8
        for (int k = 0; k < 32; ++k) {
            float4 a0 = *(const float4*)&As[k][ty * 8];
            float4 a1 = *(const float4*)&As[k][ty * 8 + 4];
            ULL ap[8];
            ap[0] = pack2(a0.x); ap[1] = pack2(a0.y); ap[2] = pack2(a0.z); ap[3] = pack2(a0.w);
            ap[4] = pack2(a1.x); ap[5] = pack2(a1.y); ap[6] = pack2(a1.z); ap[7] = pack2(a1.w);
            ulonglong2 b01 = *(const ulonglong2*)&Bs[k][tx * 8];
            ulonglong2 b23 = *(const ulonglong2*)&Bs[k][tx * 8 + 4];
            ULL bp[4] = {b01.x, b01.y, b23.x, b23.y};
#pragma unroll
            for (int i = 0; i < 8; ++i)
#pragma unroll
                for (int j = 0; j < 4; ++j)
                    fma2(acc[i][j], ap[i], bp[j]);
        }
        __syncthreads();
    }
#pragma unroll
    for (int i = 0; i < 8; ++i) {
        float2 c0 = unpack2(acc[i][0]);
        float2 c1 = unpack2(acc[i][1]);
        float2 c2 = unpack2(acc[i][2]);
        float2 c3 = unpack2(acc[i][3]);
        float* dst = out + (size_t)(rowBase + ty * 8 + i) * DD + colBase + tx * 8;
        *(float4*)dst       = make_float4(c0.x, c0.y, c1.x, c1.y);
        *(float4*)(dst + 4) = make_float4(c2.x, c2.y, c3.x, c3.y);
    }
}

// ---------------- W-GEMM: g_W = wv @ wo, 32x32 tiles, 256 blocks ------------
__global__ __launch_bounds__(256) void k_gemm_w(const float* __restrict__ wv,
                                                const float* __restrict__ wo) {
    __shared__ float As[32][36];
    __shared__ float Bs[32][32];
    int tid = threadIdx.x;
    int tx = tid & 15, ty = tid >> 4;
    int rowBase = blockIdx.y * 32, colBase = blockIdx.x * 32;
    ULL acc0 = 0ull, acc1 = 0ull;

    for (int k0 = 0; k0 < DD; k0 += 32) {
        {
            int r = tid >> 3;          // 0..31
            int c4 = (tid & 7) * 4;    // 0..28
            float4 v = *(const float4*)(wv + (size_t)(rowBase + r) * DD + k0 + c4);
            As[c4][r] = v.x; As[c4 + 1][r] = v.y; As[c4 + 2][r] = v.z; As[c4 + 3][r] = v.w;
            float4 w = *(const float4*)(wo + (size_t)(k0 + r) * DD + colBase + c4);
            *(float4*)&Bs[r][c4] = w;
        }
        __syncthreads();
#pragma unroll 8
        for (int k = 0; k < 32; ++k) {
            ULL a0 = pack2(As[k][ty * 2]);
            ULL a1 = pack2(As[k][ty * 2 + 1]);
            ULL b = *(const ULL*)&Bs[k][tx * 2];
            fma2(acc0, a0, b);
            fma2(acc1, a1, b);
        }
        __syncthreads();
    }
    float2 c0 = unpack2(acc0);
    float2 c1 = unpack2(acc1);
    *(float2*)(g_W + (size_t)(rowBase + ty * 2) * DD + colBase + tx * 2)     = c0;
    *(float2*)(g_W + (size_t)(rowBase + ty * 2 + 1) * DD + colBase + tx * 2) = c1;
}

// ---------------- K6: Vagg[b,t,:] = sum_k w_k values[b,(t+d_k)%L,:] ----------
__global__ void k_vagg(const float* __restrict__ values) {
    int t = blockIdx.x, b = blockIdx.y;
    __shared__ float w[KTOP];
    __shared__ int dl[KTOP];
    if (threadIdx.x < KTOP) { w[threadIdx.x] = g_wt[b * 8 + threadIdx.x]; dl[threadIdx.x] = g_dl[b * 8 + threadIdx.x]; }
    __syncthreads();
    int d4 = threadIdx.x;
    float4 acc = make_float4(0.f, 0.f, 0.f, 0.f);
#pragma unroll
    for (int k = 0; k < KTOP; ++k) {
        int src = (t + dl[k]) & (LL - 1);
        const float4* row = (const float4*)(values + ((size_t)b * LL + src) * DD);
        float4 v = row[d4];
        float wk = w[k];
        acc.x += wk * v.x; acc.y += wk * v.y; acc.z += wk * v.z; acc.w += wk * v.w;
    }
    ((float4*)(g_vagg + ((size_t)b * LL + t) * DD))[d4] = acc;
}

extern "C" void kernel_launch(void* const* d_in, const int* in_sizes, int n_in,
                              void* d_out, int out_size) {
    (void)in_sizes; (void)n_in; (void)out_size;
    const float* queries = (const float*)d_in[0];
    const float* keys    = (const float*)d_in[1];
    const float* values  = (const float*)d_in[2];
    const float* wq      = (const float*)d_in[3];
    const float* wk      = (const float*)d_in[4];
    const float* wv      = (const float*)d_in[5];
    const float* wo      = (const float*)d_in[6];
    float* out = (float*)d_out;

    // selection path
    k_qpart<<<dim3(BB, 2, 16), 256>>>(queries);
    k_rvec<<<BB, 512>>>(wq, wk);
    k_mc<<<dim3(LL / 8, BB), 256>>>(keys);
    k_topk<<<BB, 256>>>();

    // W = wv @ wo (512x512x512), 256 blocks
    k_gemm_w<<<dim3(DD / 32, DD / 32), 256>>>(wv, wo);

    // blended values, then out = Vagg @ W (8192x512x512)
    k_vagg<<<dim3(LL, BB), 128>>>(values);
    k_gemm_main<<<dim3(DD / 128, (BB * LL) / 128), 256>>>(out);
}

// round 5
// speedup vs baseline: 1.5581x; 1.5581x over previous
#include <cuda_runtime.h>
#include <cuda_bf16.h>
#include <math.h>

#define BB 4
#define LL 2048
#define DD 512
#define KTOP 7
typedef unsigned long long ULL;

// ---------------- scratch (device globals; no allocation allowed) ----------
__device__ float g_part[BB * 16 * DD];
__device__ float g_r[BB * DD];
__device__ float g_mc[BB * LL];
__device__ float g_wt[BB * 8];
__device__ int   g_dl[BB * 8];
__device__ float g_W[DD * DD];
__device__ float g_vagg[(size_t)BB * LL * DD];

// ---------------- packed f32x2 helpers --------------------------------------
__device__ __forceinline__ ULL pack2(float x) {
    ULL r; unsigned u = __float_as_uint(x);
    asm("mov.b64 %0, {%1, %1};" : "=l"(r) : "r"(u));
    return r;
}
__device__ __forceinline__ void fma2(ULL& d, ULL a, ULL b) {
    asm("fma.rn.f32x2 %0, %1, %2, %0;" : "+l"(d) : "l"(a), "l"(b));
}
__device__ __forceinline__ float2 unpack2(ULL v) {
    float2 f;
    asm("mov.b64 {%0, %1}, %2;" : "=f"(f.x), "=f"(f.y) : "l"(v));
    return f;
}

// ---------------- K1: partial column-sums of queries ------------------------
__global__ void k_qpart(const float* __restrict__ q) {
    int b = blockIdx.x, dchunk = blockIdx.y, ts = blockIdx.z;
    int d = dchunk * 256 + threadIdx.x;
    const float* base = q + (size_t)b * LL * DD + (size_t)(ts * 128) * DD + d;
    float s = 0.f;
#pragma unroll 8
    for (int t = 0; t < 128; ++t) s += base[(size_t)t * DD];
    g_part[(b * 16 + ts) * DD + d] = s;
}

// ---------------- K2: r[b] = wk @ (qbar @ wq) * 1/16384 ---------------------
__global__ void k_rvec(const float* __restrict__ wq, const float* __restrict__ wk) {
    __shared__ float qb[DD];
    __shared__ float qs[DD];
    int b = blockIdx.x, tid = threadIdx.x;
    float s = 0.f;
#pragma unroll
    for (int p = 0; p < 16; ++p) s += g_part[(b * 16 + p) * DD + tid];
    qb[tid] = s;
    __syncthreads();
    float acc = 0.f;
    for (int c = 0; c < DD; ++c) acc += qb[c] * wq[(size_t)c * DD + tid];
    qs[tid] = acc;
    __syncthreads();
    const float4* wkr = (const float4*)(wk + (size_t)tid * DD);
    float r = 0.f;
#pragma unroll 4
    for (int d4 = 0; d4 < DD / 4; ++d4) {
        float4 v = wkr[d4];
        r += v.x * qs[d4 * 4] + v.y * qs[d4 * 4 + 1] + v.z * qs[d4 * 4 + 2] + v.w * qs[d4 * 4 + 3];
    }
    g_r[b * DD + tid] = r * (1.0f / (8.0f * 2048.0f));
}

// ---------------- K3: mean_corr[b,j] = keys[b,j,:] . r[b] -------------------
__global__ void k_mc(const float* __restrict__ keys) {
    __shared__ float rs[DD];
    int b = blockIdx.y, tid = threadIdx.x;
    rs[tid] = g_r[b * DD + tid];
    rs[tid + 256] = g_r[b * DD + tid + 256];
    __syncthreads();
    int warp = tid >> 5, lane = tid & 31;
    int j = blockIdx.x * 8 + warp;
    const float* kr = keys + ((size_t)b * LL + j) * DD;
    float acc = 0.f;
#pragma unroll
    for (int i = 0; i < 16; ++i) acc += kr[lane + 32 * i] * rs[lane + 32 * i];
#pragma unroll
    for (int o = 16; o; o >>= 1) acc += __shfl_down_sync(0xffffffffu, acc, o);
    if (lane == 0) g_mc[b * LL + j] = acc;
}

// ---------------- K4: top-7 + softmax, log-merge ----------------------------
__device__ __forceinline__ bool topgt(float a, int ia, float b, int ib) {
    return a > b || (a == b && ia < ib);  // lax.top_k tie-break: lower index
}
__global__ void k_topk() {
    int b = blockIdx.x, tid = threadIdx.x;
    __shared__ float sv[256][8];
    __shared__ int   si[256][8];
    float v[KTOP]; int ix[KTOP];
#pragma unroll
    for (int j = 0; j < KTOP; ++j) { v[j] = -INFINITY; ix[j] = 0x7fffffff; }
    const float* mc = g_mc + b * LL;
#pragma unroll
    for (int it = 0; it < LL / 256; ++it) {
        int i = tid + it * 256;
        float x = mc[i];
        if (topgt(x, i, v[KTOP - 1], ix[KTOP - 1])) {
            float cv = x; int ci = i;
#pragma unroll
            for (int j = 0; j < KTOP; ++j) {
                if (topgt(cv, ci, v[j], ix[j])) {
                    float tv = v[j]; int ti = ix[j];
                    v[j] = cv; ix[j] = ci;
                    cv = tv; ci = ti;
                }
            }
        }
    }
#pragma unroll
    for (int j = 0; j < KTOP; ++j) { sv[tid][j] = v[j]; si[tid][j] = ix[j]; }
    __syncthreads();
    for (int s = 128; s >= 1; s >>= 1) {
        if (tid < s) {
            float mv[KTOP]; int mi[KTOP];
            int p = 0, q = 0;
#pragma unroll
            for (int r = 0; r < KTOP; ++r) {
                float av = sv[tid][p], bv2 = sv[tid + s][q];
                int   ai = si[tid][p], bi2 = si[tid + s][q];
                if (topgt(av, ai, bv2, bi2)) { mv[r] = av; mi[r] = ai; ++p; }
                else                          { mv[r] = bv2; mi[r] = bi2; ++q; }
            }
#pragma unroll
            for (int r = 0; r < KTOP; ++r) { sv[tid][r] = mv[r]; si[tid][r] = mi[r]; }
        }
        __syncthreads();
    }
    if (tid == 0) {
        float m = sv[0][0];
        float e[KTOP], ssum = 0.f;
#pragma unroll
        for (int i = 0; i < KTOP; ++i) { e[i] = expf(sv[0][i] - m); ssum += e[i]; }
        float inv = 1.0f / ssum;
#pragma unroll
        for (int i = 0; i < KTOP; ++i) { g_wt[b * 8 + i] = e[i] * inv; g_dl[b * 8 + i] = si[0][i]; }
    }
}

// ---------------- main GEMM: out = g_vagg @ g_W, f32x2, 128x128x32 ----------
// 256 threads, 8x8 per thread (8 rows x 4 f32x2 col-pairs).
// NOTE: no min-blocks clause -> up to 255 regs, no spills (R4 lesson).
__global__ __launch_bounds__(256) void k_gemm_main(float* __restrict__ out) {
    __shared__ float As[32][132];   // transposed A slab, padded
    __shared__ float Bs[32][128];
    const float* A = g_vagg;
    const float* B = g_W;
    int tid = threadIdx.x;
    int tx = tid & 15, ty = tid >> 4;
    int rowBase = blockIdx.y * 128, colBase = blockIdx.x * 128;
    ULL acc[8][4];
#pragma unroll
    for (int i = 0; i < 8; ++i)
#pragma unroll
        for (int j = 0; j < 4; ++j) acc[i][j] = 0ull;

    for (int k0 = 0; k0 < DD; k0 += 32) {
#pragma unroll
        for (int i = 0; i < 4; ++i) {
            int idx = tid + i * 256;
            int r = idx >> 3;           // 0..127
            int c4 = (idx & 7) * 4;     // 0..28
            float4 v = *(const float4*)(A + (size_t)(rowBase + r) * DD + k0 + c4);
            As[c4][r] = v.x; As[c4 + 1][r] = v.y; As[c4 + 2][r] = v.z; As[c4 + 3][r] = v.w;
        }
#pragma unroll
        for (int i = 0; i < 4; ++i) {
            int idx = tid + i * 256;
            int r = idx >> 5;           // 0..31
            int c4 = (idx & 31) * 4;    // 0..124
            *(float4*)&Bs[r][c4] = *(const float4*)(B + (size_t)(k0 + r) * DD + colBase + c4);
        }
        __syncthreads();
#pragma unroll 8
        for (int k = 0; k < 32; ++k) {
            float4 a0 = *(const float4*)&As[k][ty * 8];
            float4 a1 = *(const float4*)&As[k][ty * 8 + 4];
            ULL ap[8];
            ap[0] = pack2(a0.x); ap[1] = pack2(a0.y); ap[2] = pack2(a0.z); ap[3] = pack2(a0.w);
            ap[4] = pack2(a1.x); ap[5] = pack2(a1.y); ap[6] = pack2(a1.z); ap[7] = pack2(a1.w);
            ulonglong2 b01 = *(const ulonglong2*)&Bs[k][tx * 8];
            ulonglong2 b23 = *(const ulonglong2*)&Bs[k][tx * 8 + 4];
            ULL bp[4] = {b01.x, b01.y, b23.x, b23.y};
#pragma unroll
            for (int i = 0; i < 8; ++i)
#pragma unroll
                for (int j = 0; j < 4; ++j)
                    fma2(acc[i][j], ap[i], bp[j]);
        }
        __syncthreads();
    }
#pragma unroll
    for (int i = 0; i < 8; ++i) {
        float2 c0 = unpack2(acc[i][0]);
        float2 c1 = unpack2(acc[i][1]);
        float2 c2 = unpack2(acc[i][2]);
        float2 c3 = unpack2(acc[i][3]);
        float* dst = out + (size_t)(rowBase + ty * 8 + i) * DD + colBase + tx * 8;
        *(float4*)dst       = make_float4(c0.x, c0.y, c1.x, c1.y);
        *(float4*)(dst + 4) = make_float4(c2.x, c2.y, c3.x, c3.y);
    }
}

// ---------------- W-GEMM: g_W = wv @ wo, 32x32 tiles, 256 blocks ------------
__global__ __launch_bounds__(256) void k_gemm_w(const float* __restrict__ wv,
                                                const float* __restrict__ wo) {
    __shared__ float As[32][36];
    __shared__ float Bs[32][32];
    int tid = threadIdx.x;
    int tx = tid & 15, ty = tid >> 4;
    int rowBase = blockIdx.y * 32, colBase = blockIdx.x * 32;
    ULL acc0 = 0ull, acc1 = 0ull;

    for (int k0 = 0; k0 < DD; k0 += 32) {
        {
            int r = tid >> 3;          // 0..31
            int c4 = (tid & 7) * 4;    // 0..28
            float4 v = *(const float4*)(wv + (size_t)(rowBase + r) * DD + k0 + c4);
            As[c4][r] = v.x; As[c4 + 1][r] = v.y; As[c4 + 2][r] = v.z; As[c4 + 3][r] = v.w;
            float4 w = *(const float4*)(wo + (size_t)(k0 + r) * DD + colBase + c4);
            *(float4*)&Bs[r][c4] = w;
        }
        __syncthreads();
#pragma unroll 8
        for (int k = 0; k < 32; ++k) {
            ULL a0 = pack2(As[k][ty * 2]);
            ULL a1 = pack2(As[k][ty * 2 + 1]);
            ULL b = *(const ULL*)&Bs[k][tx * 2];
            fma2(acc0, a0, b);
            fma2(acc1, a1, b);
        }
        __syncthreads();
    }
    float2 c0 = unpack2(acc0);
    float2 c1 = unpack2(acc1);
    *(float2*)(g_W + (size_t)(rowBase + ty * 2) * DD + colBase + tx * 2)     = c0;
    *(float2*)(g_W + (size_t)(rowBase + ty * 2 + 1) * DD + colBase + tx * 2) = c1;
}

// ---------------- K6: Vagg[b,t,:] = sum_k w_k values[b,(t+d_k)%L,:] ----------
__global__ void k_vagg(const float* __restrict__ values) {
    int t = blockIdx.x, b = blockIdx.y;
    __shared__ float w[KTOP];
    __shared__ int dl[KTOP];
    if (threadIdx.x < KTOP) { w[threadIdx.x] = g_wt[b * 8 + threadIdx.x]; dl[threadIdx.x] = g_dl[b * 8 + threadIdx.x]; }
    __syncthreads();
    int d4 = threadIdx.x;
    float4 acc = make_float4(0.f, 0.f, 0.f, 0.f);
#pragma unroll
    for (int k = 0; k < KTOP; ++k) {
        int src = (t + dl[k]) & (LL - 1);
        const float4* row = (const float4*)(values + ((size_t)b * LL + src) * DD);
        float4 v = row[d4];
        float wk = w[k];
        acc.x += wk * v.x; acc.y += wk * v.y; acc.z += wk * v.z; acc.w += wk * v.w;
    }
    ((float4*)(g_vagg + ((size_t)b * LL + t) * DD))[d4] = acc;
}

extern "C" void kernel_launch(void* const* d_in, const int* in_sizes, int n_in,
                              void* d_out, int out_size) {
    (void)in_sizes; (void)n_in; (void)out_size;
    const float* queries = (const float*)d_in[0];
    const float* keys    = (const float*)d_in[1];
    const float* values  = (const float*)d_in[2];
    const float* wq      = (const float*)d_in[3];
    const float* wk      = (const float*)d_in[4];
    const float* wv      = (const float*)d_in[5];
    const float* wo      = (const float*)d_in[6];
    float* out = (float*)d_out;

    // selection path
    k_qpart<<<dim3(BB, 2, 16), 256>>>(queries);
    k_rvec<<<BB, 512>>>(wq, wk);
    k_mc<<<dim3(LL / 8, BB), 256>>>(keys);
    k_topk<<<BB, 256>>>();

    // W = wv @ wo (512x512x512)
    k_gemm_w<<<dim3(DD / 32, DD / 32), 256>>>(wv, wo);

    // blended values, then out = Vagg @ W (8192x512x512)
    k_vagg<<<dim3(LL, BB), 128>>>(values);
    k_gemm_main<<<dim3(DD / 128, (BB * LL) / 128), 256>>>(out);
}

// round 8
// speedup vs baseline: 1.9528x; 1.2533x over previous
#include <cuda_runtime.h>
#include <cuda_bf16.h>
#include <math.h>
#include <stdint.h>

#define BB 4
#define LL 2048
#define DD 512
#define KTOP 7
typedef unsigned long long ULL;

// ---------------- scratch (device globals; no allocation allowed) ----------
__device__ float g_part[BB * 16 * DD];
__device__ float g_r[BB * DD];
__device__ float g_mc[BB * LL];
__device__ float g_wt[BB * 8];
__device__ int   g_dl[BB * 8];
__device__ float g_W[DD * DD];
__device__ __nv_bfloat16 g_Ahi[(size_t)BB * LL * DD];
__device__ __nv_bfloat16 g_Alo[(size_t)BB * LL * DD];
__device__ __nv_bfloat16 g_Bhi[DD * DD];   // W transposed: [N][K] (col-major B)
__device__ __nv_bfloat16 g_Blo[DD * DD];

// ---------------- f32x2 helpers (for the small W GEMM) ----------------------
__device__ __forceinline__ ULL pack2(float x) {
    ULL r; unsigned u = __float_as_uint(x);
    asm("mov.b64 %0, {%1, %1};" : "=l"(r) : "r"(u));
    return r;
}
__device__ __forceinline__ void fma2(ULL& d, ULL a, ULL b) {
    asm("fma.rn.f32x2 %0, %1, %2, %0;" : "+l"(d) : "l"(a), "l"(b));
}
__device__ __forceinline__ float2 unpack2(ULL v) {
    float2 f;
    asm("mov.b64 {%0, %1}, %2;" : "=f"(f.x), "=f"(f.y) : "l"(v));
    return f;
}
__device__ __forceinline__ uint32_t smem_u32(const void* p) {
    uint32_t a;
    asm("{ .reg .u64 t; cvta.to.shared.u64 t, %1; cvt.u32.u64 %0, t; }" : "=r"(a) : "l"(p));
    return a;
}

// ---------------- mma.sync helpers ------------------------------------------
__device__ __forceinline__ void ldsm_x4(uint32_t* d, uint32_t addr) {
    asm volatile("ldmatrix.sync.aligned.m8n8.x4.shared.b16 {%0,%1,%2,%3}, [%4];"
                 : "=r"(d[0]), "=r"(d[1]), "=r"(d[2]), "=r"(d[3]) : "r"(addr));
}
__device__ __forceinline__ void ldsm_x2(uint32_t* d, uint32_t addr) {
    asm volatile("ldmatrix.sync.aligned.m8n8.x2.shared.b16 {%0,%1}, [%2];"
                 : "=r"(d[0]), "=r"(d[1]) : "r"(addr));
}
__device__ __forceinline__ void mma_bf16(float* c, const uint32_t* a, const uint32_t* b) {
    asm volatile(
        "mma.sync.aligned.m16n8k16.row.col.f32.bf16.bf16.f32 "
        "{%0,%1,%2,%3}, {%4,%5,%6,%7}, {%8,%9}, {%0,%1,%2,%3};"
        : "+f"(c[0]), "+f"(c[1]), "+f"(c[2]), "+f"(c[3])
        : "r"(a[0]), "r"(a[1]), "r"(a[2]), "r"(a[3]), "r"(b[0]), "r"(b[1]));
}

// ---------------- K1: partial column-sums of queries ------------------------
__global__ void k_qpart(const float* __restrict__ q) {
    int b = blockIdx.x, dchunk = blockIdx.y, ts = blockIdx.z;
    int d = dchunk * 256 + threadIdx.x;
    const float* base = q + (size_t)b * LL * DD + (size_t)(ts * 128) * DD + d;
    float s = 0.f;
#pragma unroll 8
    for (int t = 0; t < 128; ++t) s += base[(size_t)t * DD];
    g_part[(b * 16 + ts) * DD + d] = s;
}

// ---------------- K2: r[b] = wk @ (qbar @ wq) * 1/16384 ---------------------
__global__ void k_rvec(const float* __restrict__ wq, const float* __restrict__ wk) {
    __shared__ float qb[DD];
    __shared__ float qs[DD];
    int b = blockIdx.x, tid = threadIdx.x;
    float s = 0.f;
#pragma unroll
    for (int p = 0; p < 16; ++p) s += g_part[(b * 16 + p) * DD + tid];
    qb[tid] = s;
    __syncthreads();
    float acc = 0.f;
    for (int c = 0; c < DD; ++c) acc += qb[c] * wq[(size_t)c * DD + tid];
    qs[tid] = acc;
    __syncthreads();
    const float4* wkr = (const float4*)(wk + (size_t)tid * DD);
    float r = 0.f;
#pragma unroll 4
    for (int d4 = 0; d4 < DD / 4; ++d4) {
        float4 v = wkr[d4];
        r += v.x * qs[d4 * 4] + v.y * qs[d4 * 4 + 1] + v.z * qs[d4 * 4 + 2] + v.w * qs[d4 * 4 + 3];
    }
    g_r[b * DD + tid] = r * (1.0f / (8.0f * 2048.0f));
}

// ---------------- K3: mean_corr[b,j] = keys[b,j,:] . r[b] -------------------
__global__ void k_mc(const float* __restrict__ keys) {
    __shared__ float rs[DD];
    int b = blockIdx.y, tid = threadIdx.x;
    rs[tid] = g_r[b * DD + tid];
    rs[tid + 256] = g_r[b * DD + tid + 256];
    __syncthreads();
    int warp = tid >> 5, lane = tid & 31;
    int j = blockIdx.x * 8 + warp;
    const float* kr = keys + ((size_t)b * LL + j) * DD;
    float acc = 0.f;
#pragma unroll
    for (int i = 0; i < 16; ++i) acc += kr[lane + 32 * i] * rs[lane + 32 * i];
#pragma unroll
    for (int o = 16; o; o >>= 1) acc += __shfl_down_sync(0xffffffffu, acc, o);
    if (lane == 0) g_mc[b * LL + j] = acc;
}

// ---------------- K4: top-7 + softmax, log-merge ----------------------------
__device__ __forceinline__ bool topgt(float a, int ia, float b, int ib) {
    return a > b || (a == b && ia < ib);  // lax.top_k tie-break: lower index
}
__global__ void k_topk() {
    int b = blockIdx.x, tid = threadIdx.x;
    __shared__ float sv[256][8];
    __shared__ int   si[256][8];
    float v[KTOP]; int ix[KTOP];
#pragma unroll
    for (int j = 0; j < KTOP; ++j) { v[j] = -INFINITY; ix[j] = 0x7fffffff; }
    const float* mc = g_mc + b * LL;
#pragma unroll
    for (int it = 0; it < LL / 256; ++it) {
        int i = tid + it * 256;
        float x = mc[i];
        if (topgt(x, i, v[KTOP - 1], ix[KTOP - 1])) {
            float cv = x; int ci = i;
#pragma unroll
            for (int j = 0; j < KTOP; ++j) {
                if (topgt(cv, ci, v[j], ix[j])) {
                    float tv = v[j]; int ti = ix[j];
                    v[j] = cv; ix[j] = ci;
                    cv = tv; ci = ti;
                }
            }
        }
    }
#pragma unroll
    for (int j = 0; j < KTOP; ++j) { sv[tid][j] = v[j]; si[tid][j] = ix[j]; }
    __syncthreads();
    for (int s = 128; s >= 1; s >>= 1) {
        if (tid < s) {
            float mv[KTOP]; int mi[KTOP];
            int p = 0, q = 0;
#pragma unroll
            for (int r = 0; r < KTOP; ++r) {
                float av = sv[tid][p], bv2 = sv[tid + s][q];
                int   ai = si[tid][p], bi2 = si[tid + s][q];
                if (topgt(av, ai, bv2, bi2)) { mv[r] = av; mi[r] = ai; ++p; }
                else                          { mv[r] = bv2; mi[r] = bi2; ++q; }
            }
#pragma unroll
            for (int r = 0; r < KTOP; ++r) { sv[tid][r] = mv[r]; si[tid][r] = mi[r]; }
        }
        __syncthreads();
    }
    if (tid == 0) {
        float m = sv[0][0];
        float e[KTOP], ssum = 0.f;
#pragma unroll
        for (int i = 0; i < KTOP; ++i) { e[i] = expf(sv[0][i] - m); ssum += e[i]; }
        float inv = 1.0f / ssum;
#pragma unroll
        for (int i = 0; i < KTOP; ++i) { g_wt[b * 8 + i] = e[i] * inv; g_dl[b * 8 + i] = si[0][i]; }
    }
}

// ---------------- W-GEMM: g_W = wv @ wo, fp32 f32x2, 32x32 tiles ------------
__global__ __launch_bounds__(256) void k_gemm_w(const float* __restrict__ wv,
                                                const float* __restrict__ wo) {
    __shared__ float As[32][36];
    __shared__ float Bs[32][32];
    int tid = threadIdx.x;
    int tx = tid & 15, ty = tid >> 4;
    int rowBase = blockIdx.y * 32, colBase = blockIdx.x * 32;
    ULL acc0 = 0ull, acc1 = 0ull;
    for (int k0 = 0; k0 < DD; k0 += 32) {
        {
            int r = tid >> 3;
            int c4 = (tid & 7) * 4;
            float4 v = *(const float4*)(wv + (size_t)(rowBase + r) * DD + k0 + c4);
            As[c4][r] = v.x; As[c4 + 1][r] = v.y; As[c4 + 2][r] = v.z; As[c4 + 3][r] = v.w;
            float4 w = *(const float4*)(wo + (size_t)(k0 + r) * DD + colBase + c4);
            *(float4*)&Bs[r][c4] = w;
        }
        __syncthreads();
#pragma unroll 8
        for (int k = 0; k < 32; ++k) {
            ULL a0 = pack2(As[k][ty * 2]);
            ULL a1 = pack2(As[k][ty * 2 + 1]);
            ULL b = *(const ULL*)&Bs[k][tx * 2];
            fma2(acc0, a0, b);
            fma2(acc1, a1, b);
        }
        __syncthreads();
    }
    float2 c0 = unpack2(acc0);
    float2 c1 = unpack2(acc1);
    *(float2*)(g_W + (size_t)(rowBase + ty * 2) * DD + colBase + tx * 2)     = c0;
    *(float2*)(g_W + (size_t)(rowBase + ty * 2 + 1) * DD + colBase + tx * 2) = c1;
}

// ---------------- K5b: transpose + bf16-split W -> g_Bhi/g_Blo [N][K] -------
__global__ __launch_bounds__(256) void k_wsplit() {
    __shared__ float tile[32][33];
    int n0 = blockIdx.x * 32, k0 = blockIdx.y * 32;
    int tx = threadIdx.x & 31, ty = threadIdx.x >> 5;  // ty 0..7
#pragma unroll
    for (int i = 0; i < 32; i += 8)
        tile[ty + i][tx] = g_W[(size_t)(k0 + ty + i) * DD + n0 + tx];
    __syncthreads();
#pragma unroll
    for (int i = 0; i < 32; i += 8) {
        float x = tile[tx][ty + i];  // W[k0+tx][n0+ty+i]
        __nv_bfloat16 h = __float2bfloat16(x);
        __nv_bfloat16 l = __float2bfloat16(x - __bfloat162float(h));
        size_t dst = (size_t)(n0 + ty + i) * DD + k0 + tx;
        g_Bhi[dst] = h;
        g_Blo[dst] = l;
    }
}

// ---------------- K6: Vagg blended values -> bf16 hi/lo A -------------------
__global__ void k_vagg(const float* __restrict__ values) {
    int t = blockIdx.x, b = blockIdx.y;
    __shared__ float w[KTOP];
    __shared__ int dl[KTOP];
    if (threadIdx.x < KTOP) { w[threadIdx.x] = g_wt[b * 8 + threadIdx.x]; dl[threadIdx.x] = g_dl[b * 8 + threadIdx.x]; }
    __syncthreads();
    int d4 = threadIdx.x;
    float4 acc = make_float4(0.f, 0.f, 0.f, 0.f);
#pragma unroll
    for (int k = 0; k < KTOP; ++k) {
        int src = (t + dl[k]) & (LL - 1);
        const float4* row = (const float4*)(values + ((size_t)b * LL + src) * DD);
        float4 v = row[d4];
        float wk = w[k];
        acc.x += wk * v.x; acc.y += wk * v.y; acc.z += wk * v.z; acc.w += wk * v.w;
    }
    size_t base = ((size_t)b * LL + t) * DD + d4 * 4;
    float a[4] = {acc.x, acc.y, acc.z, acc.w};
    __nv_bfloat16 h[4], l[4];
#pragma unroll
    for (int j = 0; j < 4; ++j) {
        h[j] = __float2bfloat16(a[j]);
        l[j] = __float2bfloat16(a[j] - __bfloat162float(h[j]));
    }
    *(__nv_bfloat162*)(g_Ahi + base)     = __nv_bfloat162(h[0], h[1]);
    *(__nv_bfloat162*)(g_Ahi + base + 2) = __nv_bfloat162(h[2], h[3]);
    *(__nv_bfloat162*)(g_Alo + base)     = __nv_bfloat162(l[0], l[1]);
    *(__nv_bfloat162*)(g_Alo + base + 2) = __nv_bfloat162(l[2], l[3]);
}

// ---------------- main GEMM: mma.sync bf16-split, 128x128 tile, kchunk 32 ---
// 8 warps (2x4); warp computes 64x32 via 4x4 m16n8k16 tiles.
// smem: 4 tiles of [128 rows][32 bf16] (64B rows), XOR-swizzled 16B segments:
// seg' = seg ^ ((row>>1)&3)  -> conflict-free ldmatrix and stores.
__global__ __launch_bounds__(256) void k_gemm_mma(float* __restrict__ out) {
    __shared__ __nv_bfloat16 sAh[128 * 32];
    __shared__ __nv_bfloat16 sAl[128 * 32];
    __shared__ __nv_bfloat16 sBh[128 * 32];
    __shared__ __nv_bfloat16 sBl[128 * 32];
    int tid = threadIdx.x;
    int wid = tid >> 5, lane = tid & 31;
    int warp_m = wid & 1, warp_n = wid >> 1;
    int rowBase = blockIdx.y * 128, colBase = blockIdx.x * 128;

    const __nv_bfloat16* gAh = g_Ahi + (size_t)rowBase * DD;
    const __nv_bfloat16* gAl = g_Alo + (size_t)rowBase * DD;
    const __nv_bfloat16* gBh = g_Bhi + (size_t)colBase * DD;
    const __nv_bfloat16* gBl = g_Blo + (size_t)colBase * DD;

    uint32_t baseAh = smem_u32(sAh), baseAl = smem_u32(sAl);
    uint32_t baseBh = smem_u32(sBh), baseBl = smem_u32(sBl);

    float acc[4][4][4];
#pragma unroll
    for (int mt = 0; mt < 4; ++mt)
#pragma unroll
        for (int nt = 0; nt < 4; ++nt)
#pragma unroll
            for (int e = 0; e < 4; ++e) acc[mt][nt][e] = 0.f;

    // per-lane ldmatrix address components
    int amat = lane >> 3;                      // 0..3
    int a_rin = (lane & 7) + ((amat & 1) << 3); // row within m16
    int a_ksel = amat >> 1;                    // 0/1 -> +8 k
    int b_l4 = lane & 15;
    int b_rin = b_l4 & 7;                      // row within n8
    int b_ksel = b_l4 >> 3;                    // 0/1 -> +8 k

    for (int kc = 0; kc < DD / 32; ++kc) {
        __syncthreads();
#pragma unroll
        for (int i = 0; i < 2; ++i) {
            int idx = tid + i * 256;
            int r = idx >> 2, c = idx & 3;
            int seg = c ^ ((r >> 1) & 3);
            size_t goff = (size_t)r * DD + kc * 32 + c * 8;
            uint32_t soff = (uint32_t)(r * 64 + seg * 16);
            *(uint4*)((char*)sAh + soff) = *(const uint4*)(gAh + goff);
            *(uint4*)((char*)sAl + soff) = *(const uint4*)(gAl + goff);
            *(uint4*)((char*)sBh + soff) = *(const uint4*)(gBh + goff);
            *(uint4*)((char*)sBl + soff) = *(const uint4*)(gBl + goff);
        }
        __syncthreads();
#pragma unroll
        for (int ks = 0; ks < 2; ++ks) {
            uint32_t ah[4][4], al[4][4], bh[4][2], bl[4][2];
#pragma unroll
            for (int mt = 0; mt < 4; ++mt) {
                int m = warp_m * 64 + mt * 16 + a_rin;
                int kseg = ks * 2 + a_ksel;
                int seg = kseg ^ ((m >> 1) & 3);
                uint32_t off = (uint32_t)(m * 64 + seg * 16);
                ldsm_x4(ah[mt], baseAh + off);
                ldsm_x4(al[mt], baseAl + off);
            }
#pragma unroll
            for (int nt = 0; nt < 4; ++nt) {
                int n = warp_n * 32 + nt * 8 + b_rin;
                int kseg = ks * 2 + b_ksel;
                int seg = kseg ^ ((n >> 1) & 3);
                uint32_t off = (uint32_t)(n * 64 + seg * 16);
                ldsm_x2(bh[nt], baseBh + off);
                ldsm_x2(bl[nt], baseBl + off);
            }
#pragma unroll
            for (int mt = 0; mt < 4; ++mt)
#pragma unroll
                for (int nt = 0; nt < 4; ++nt) {
                    mma_bf16(acc[mt][nt], ah[mt], bh[nt]);
                    mma_bf16(acc[mt][nt], al[mt], bh[nt]);
                    mma_bf16(acc[mt][nt], ah[mt], bl[nt]);
                }
        }
    }

    // epilogue: c-frag lane mapping r=lane/4, c=(lane%4)*2 (+8 rows for c2,c3)
    int er = lane >> 2, ec = (lane & 3) * 2;
#pragma unroll
    for (int mt = 0; mt < 4; ++mt) {
#pragma unroll
        for (int nt = 0; nt < 4; ++nt) {
            int row0 = rowBase + warp_m * 64 + mt * 16 + er;
            int col = colBase + warp_n * 32 + nt * 8 + ec;
            *(float2*)(out + (size_t)row0 * DD + col) = make_float2(acc[mt][nt][0], acc[mt][nt][1]);
            *(float2*)(out + (size_t)(row0 + 8) * DD + col) = make_float2(acc[mt][nt][2], acc[mt][nt][3]);
        }
    }
}

extern "C" void kernel_launch(void* const* d_in, const int* in_sizes, int n_in,
                              void* d_out, int out_size) {
    (void)in_sizes; (void)n_in; (void)out_size;
    const float* queries = (const float*)d_in[0];
    const float* keys    = (const float*)d_in[1];
    const float* values  = (const float*)d_in[2];
    const float* wq      = (const float*)d_in[3];
    const float* wk      = (const float*)d_in[4];
    const float* wv      = (const float*)d_in[5];
    const float* wo      = (const float*)d_in[6];
    float* out = (float*)d_out;

    // selection path
    k_qpart<<<dim3(BB, 2, 16), 256>>>(queries);
    k_rvec<<<BB, 512>>>(wq, wk);
    k_mc<<<dim3(LL / 8, BB), 256>>>(keys);
    k_topk<<<BB, 256>>>();

    // W = wv @ wo (fp32), then transpose+split to bf16 [N][K]
    k_gemm_w<<<dim3(DD / 32, DD / 32), 256>>>(wv, wo);
    k_wsplit<<<dim3(DD / 32, DD / 32), 256>>>();

    // blended values -> bf16 hi/lo, then tensor-core GEMM
    k_vagg<<<dim3(LL, BB), 128>>>(values);
    k_gemm_mma<<<dim3(DD / 128, (BB * LL) / 128), 256>>>(out);
}

// round 9
// speedup vs baseline: 2.1001x; 1.0754x over previous
#include <cuda_runtime.h>
#include <cuda_bf16.h>
#include <math.h>
#include <stdint.h>

#define BB 4
#define LL 2048
#define DD 512
#define KTOP 7
typedef unsigned long long ULL;

// ---------------- scratch (device globals; no allocation allowed) ----------
__device__ float g_part[BB * 16 * DD];
__device__ float g_r[BB * DD];
__device__ float g_mc[BB * LL];
__device__ float g_wt[BB * 8];
__device__ int   g_dl[BB * 8];
__device__ float g_W[DD * DD];
__device__ __nv_bfloat16 g_Ahi[(size_t)BB * LL * DD];
__device__ __nv_bfloat16 g_Alo[(size_t)BB * LL * DD];
__device__ __nv_bfloat16 g_Bhi[DD * DD];   // W transposed: [N][K] (col-major B)
__device__ __nv_bfloat16 g_Blo[DD * DD];

// ---------------- f32x2 helpers (for the small W GEMM) ----------------------
__device__ __forceinline__ ULL pack2(float x) {
    ULL r; unsigned u = __float_as_uint(x);
    asm("mov.b64 %0, {%1, %1};" : "=l"(r) : "r"(u));
    return r;
}
__device__ __forceinline__ void fma2(ULL& d, ULL a, ULL b) {
    asm("fma.rn.f32x2 %0, %1, %2, %0;" : "+l"(d) : "l"(a), "l"(b));
}
__device__ __forceinline__ float2 unpack2(ULL v) {
    float2 f;
    asm("mov.b64 {%0, %1}, %2;" : "=f"(f.x), "=f"(f.y) : "l"(v));
    return f;
}
__device__ __forceinline__ uint32_t smem_u32(const void* p) {
    uint32_t a;
    asm("{ .reg .u64 t; cvta.to.shared.u64 t, %1; cvt.u32.u64 %0, t; }" : "=r"(a) : "l"(p));
    return a;
}

// ---------------- mma.sync / cp.async helpers --------------------------------
__device__ __forceinline__ void ldsm_x4(uint32_t* d, uint32_t addr) {
    asm volatile("ldmatrix.sync.aligned.m8n8.x4.shared.b16 {%0,%1,%2,%3}, [%4];"
                 : "=r"(d[0]), "=r"(d[1]), "=r"(d[2]), "=r"(d[3]) : "r"(addr));
}
__device__ __forceinline__ void ldsm_x2(uint32_t* d, uint32_t addr) {
    asm volatile("ldmatrix.sync.aligned.m8n8.x2.shared.b16 {%0,%1}, [%2];"
                 : "=r"(d[0]), "=r"(d[1]) : "r"(addr));
}
__device__ __forceinline__ void mma_bf16(float* c, const uint32_t* a, const uint32_t* b) {
    asm volatile(
        "mma.sync.aligned.m16n8k16.row.col.f32.bf16.bf16.f32 "
        "{%0,%1,%2,%3}, {%4,%5,%6,%7}, {%8,%9}, {%0,%1,%2,%3};"
        : "+f"(c[0]), "+f"(c[1]), "+f"(c[2]), "+f"(c[3])
        : "r"(a[0]), "r"(a[1]), "r"(a[2]), "r"(a[3]), "r"(b[0]), "r"(b[1]));
}
__device__ __forceinline__ void cpasync16(uint32_t dst, const void* src) {
    asm volatile("cp.async.cg.shared.global [%0], [%1], 16;" :: "r"(dst), "l"(src));
}
__device__ __forceinline__ void cpasync_commit() {
    asm volatile("cp.async.commit_group;" ::: "memory");
}
__device__ __forceinline__ void cpasync_wait0() {
    asm volatile("cp.async.wait_group 0;" ::: "memory");
}

// ---------------- K1: partial column-sums of queries ------------------------
__global__ void k_qpart(const float* __restrict__ q) {
    int b = blockIdx.x, dchunk = blockIdx.y, ts = blockIdx.z;
    int d = dchunk * 256 + threadIdx.x;
    const float* base = q + (size_t)b * LL * DD + (size_t)(ts * 128) * DD + d;
    float s = 0.f;
#pragma unroll 8
    for (int t = 0; t < 128; ++t) s += base[(size_t)t * DD];
    g_part[(b * 16 + ts) * DD + d] = s;
}

// ---------------- K2: r[b] = wk @ (qbar @ wq) * 1/16384 ---------------------
__global__ void k_rvec(const float* __restrict__ wq, const float* __restrict__ wk) {
    __shared__ float qb[DD];
    __shared__ float qs[DD];
    int b = blockIdx.x, tid = threadIdx.x;
    float s = 0.f;
#pragma unroll
    for (int p = 0; p < 16; ++p) s += g_part[(b * 16 + p) * DD + tid];
    qb[tid] = s;
    __syncthreads();
    float acc = 0.f;
    for (int c = 0; c < DD; ++c) acc += qb[c] * wq[(size_t)c * DD + tid];
    qs[tid] = acc;
    __syncthreads();
    const float4* wkr = (const float4*)(wk + (size_t)tid * DD);
    float r = 0.f;
#pragma unroll 4
    for (int d4 = 0; d4 < DD / 4; ++d4) {
        float4 v = wkr[d4];
        r += v.x * qs[d4 * 4] + v.y * qs[d4 * 4 + 1] + v.z * qs[d4 * 4 + 2] + v.w * qs[d4 * 4 + 3];
    }
    g_r[b * DD + tid] = r * (1.0f / (8.0f * 2048.0f));
}

// ---------------- K3: mean_corr[b,j] = keys[b,j,:] . r[b] -------------------
__global__ void k_mc(const float* __restrict__ keys) {
    __shared__ float rs[DD];
    int b = blockIdx.y, tid = threadIdx.x;
    rs[tid] = g_r[b * DD + tid];
    rs[tid + 256] = g_r[b * DD + tid + 256];
    __syncthreads();
    int warp = tid >> 5, lane = tid & 31;
    int j = blockIdx.x * 8 + warp;
    const float* kr = keys + ((size_t)b * LL + j) * DD;
    float acc = 0.f;
#pragma unroll
    for (int i = 0; i < 16; ++i) acc += kr[lane + 32 * i] * rs[lane + 32 * i];
#pragma unroll
    for (int o = 16; o; o >>= 1) acc += __shfl_down_sync(0xffffffffu, acc, o);
    if (lane == 0) g_mc[b * LL + j] = acc;
}

// ---------------- K4: top-7 + softmax, log-merge ----------------------------
__device__ __forceinline__ bool topgt(float a, int ia, float b, int ib) {
    return a > b || (a == b && ia < ib);  // lax.top_k tie-break: lower index
}
__global__ void k_topk() {
    int b = blockIdx.x, tid = threadIdx.x;
    __shared__ float sv[256][8];
    __shared__ int   si[256][8];
    float v[KTOP]; int ix[KTOP];
#pragma unroll
    for (int j = 0; j < KTOP; ++j) { v[j] = -INFINITY; ix[j] = 0x7fffffff; }
    const float* mc = g_mc + b * LL;
#pragma unroll
    for (int it = 0; it < LL / 256; ++it) {
        int i = tid + it * 256;
        float x = mc[i];
        if (topgt(x, i, v[KTOP - 1], ix[KTOP - 1])) {
            float cv = x; int ci = i;
#pragma unroll
            for (int j = 0; j < KTOP; ++j) {
                if (topgt(cv, ci, v[j], ix[j])) {
                    float tv = v[j]; int ti = ix[j];
                    v[j] = cv; ix[j] = ci;
                    cv = tv; ci = ti;
                }
            }
        }
    }
#pragma unroll
    for (int j = 0; j < KTOP; ++j) { sv[tid][j] = v[j]; si[tid][j] = ix[j]; }
    __syncthreads();
    for (int s = 128; s >= 1; s >>= 1) {
        if (tid < s) {
            float mv[KTOP]; int mi[KTOP];
            int p = 0, q = 0;
#pragma unroll
            for (int r = 0; r < KTOP; ++r) {
                float av = sv[tid][p], bv2 = sv[tid + s][q];
                int   ai = si[tid][p], bi2 = si[tid + s][q];
                if (topgt(av, ai, bv2, bi2)) { mv[r] = av; mi[r] = ai; ++p; }
                else                          { mv[r] = bv2; mi[r] = bi2; ++q; }
            }
#pragma unroll
            for (int r = 0; r < KTOP; ++r) { sv[tid][r] = mv[r]; si[tid][r] = mi[r]; }
        }
        __syncthreads();
    }
    if (tid == 0) {
        float m = sv[0][0];
        float e[KTOP], ssum = 0.f;
#pragma unroll
        for (int i = 0; i < KTOP; ++i) { e[i] = expf(sv[0][i] - m); ssum += e[i]; }
        float inv = 1.0f / ssum;
#pragma unroll
        for (int i = 0; i < KTOP; ++i) { g_wt[b * 8 + i] = e[i] * inv; g_dl[b * 8 + i] = si[0][i]; }
    }
}

// ---------------- W-GEMM: g_W = wv @ wo, fp32 f32x2, 32x32 tiles ------------
__global__ __launch_bounds__(256) void k_gemm_w(const float* __restrict__ wv,
                                                const float* __restrict__ wo) {
    __shared__ float As[32][36];
    __shared__ float Bs[32][32];
    int tid = threadIdx.x;
    int tx = tid & 15, ty = tid >> 4;
    int rowBase = blockIdx.y * 32, colBase = blockIdx.x * 32;
    ULL acc0 = 0ull, acc1 = 0ull;
    for (int k0 = 0; k0 < DD; k0 += 32) {
        {
            int r = tid >> 3;
            int c4 = (tid & 7) * 4;
            float4 v = *(const float4*)(wv + (size_t)(rowBase + r) * DD + k0 + c4);
            As[c4][r] = v.x; As[c4 + 1][r] = v.y; As[c4 + 2][r] = v.z; As[c4 + 3][r] = v.w;
            float4 w = *(const float4*)(wo + (size_t)(k0 + r) * DD + colBase + c4);
            *(float4*)&Bs[r][c4] = w;
        }
        __syncthreads();
#pragma unroll 8
        for (int k = 0; k < 32; ++k) {
            ULL a0 = pack2(As[k][ty * 2]);
            ULL a1 = pack2(As[k][ty * 2 + 1]);
            ULL b = *(const ULL*)&Bs[k][tx * 2];
            fma2(acc0, a0, b);
            fma2(acc1, a1, b);
        }
        __syncthreads();
    }
    float2 c0 = unpack2(acc0);
    float2 c1 = unpack2(acc1);
    *(float2*)(g_W + (size_t)(rowBase + ty * 2) * DD + colBase + tx * 2)     = c0;
    *(float2*)(g_W + (size_t)(rowBase + ty * 2 + 1) * DD + colBase + tx * 2) = c1;
}

// ---------------- K5b: transpose + bf16-split W -> g_Bhi/g_Blo [N][K] -------
__global__ __launch_bounds__(256) void k_wsplit() {
    __shared__ float tile[32][33];
    int n0 = blockIdx.x * 32, k0 = blockIdx.y * 32;
    int tx = threadIdx.x & 31, ty = threadIdx.x >> 5;  // ty 0..7
#pragma unroll
    for (int i = 0; i < 32; i += 8)
        tile[ty + i][tx] = g_W[(size_t)(k0 + ty + i) * DD + n0 + tx];
    __syncthreads();
#pragma unroll
    for (int i = 0; i < 32; i += 8) {
        float x = tile[tx][ty + i];  // W[k0+tx][n0+ty+i]
        __nv_bfloat16 h = __float2bfloat16(x);
        __nv_bfloat16 l = __float2bfloat16(x - __bfloat162float(h));
        size_t dst = (size_t)(n0 + ty + i) * DD + k0 + tx;
        g_Bhi[dst] = h;
        g_Blo[dst] = l;
    }
}

// ---------------- K6: Vagg blended values -> bf16 hi/lo A -------------------
__global__ void k_vagg(const float* __restrict__ values) {
    int t = blockIdx.x, b = blockIdx.y;
    __shared__ float w[KTOP];
    __shared__ int dl[KTOP];
    if (threadIdx.x < KTOP) { w[threadIdx.x] = g_wt[b * 8 + threadIdx.x]; dl[threadIdx.x] = g_dl[b * 8 + threadIdx.x]; }
    __syncthreads();
    int d4 = threadIdx.x;
    float4 acc = make_float4(0.f, 0.f, 0.f, 0.f);
#pragma unroll
    for (int k = 0; k < KTOP; ++k) {
        int src = (t + dl[k]) & (LL - 1);
        const float4* row = (const float4*)(values + ((size_t)b * LL + src) * DD);
        float4 v = row[d4];
        float wk = w[k];
        acc.x += wk * v.x; acc.y += wk * v.y; acc.z += wk * v.z; acc.w += wk * v.w;
    }
    size_t base = ((size_t)b * LL + t) * DD + d4 * 4;
    float a[4] = {acc.x, acc.y, acc.z, acc.w};
    __nv_bfloat16 h[4], l[4];
#pragma unroll
    for (int j = 0; j < 4; ++j) {
        h[j] = __float2bfloat16(a[j]);
        l[j] = __float2bfloat16(a[j] - __bfloat162float(h[j]));
    }
    *(__nv_bfloat162*)(g_Ahi + base)     = __nv_bfloat162(h[0], h[1]);
    *(__nv_bfloat162*)(g_Ahi + base + 2) = __nv_bfloat162(h[2], h[3]);
    *(__nv_bfloat162*)(g_Alo + base)     = __nv_bfloat162(l[0], l[1]);
    *(__nv_bfloat162*)(g_Alo + base + 2) = __nv_bfloat162(l[2], l[3]);
}

// ---------------- main GEMM: mma.sync bf16-split, cp.async 2-stage pipeline -
// 128x128 CTA tile, K-chunk 16, 8 warps (2x4), warp = 64x32 via 4x4 mma tiles.
// smem: 2 stages x 4 tiles x [128 rows x 16 bf16] (32B rows). Swizzle:
// seg' = seg ^ ((row>>2)&1) on 16B segments -> conflict-free ldmatrix.
#define TILE_BYTES 4096
__global__ __launch_bounds__(256) void k_gemm_mma(float* __restrict__ out) {
    __shared__ char smem_raw[2 * 4 * TILE_BYTES];
    int tid = threadIdx.x;
    int wid = tid >> 5, lane = tid & 31;
    int warp_m = wid & 1, warp_n = wid >> 1;
    int rowBase = blockIdx.y * 128, colBase = blockIdx.x * 128;

    const __nv_bfloat16* src[4] = {
        g_Ahi + (size_t)rowBase * DD,
        g_Alo + (size_t)rowBase * DD,
        g_Bhi + (size_t)colBase * DD,
        g_Blo + (size_t)colBase * DD };

    uint32_t sb = smem_u32(smem_raw);

    float acc[4][4][4];
#pragma unroll
    for (int mt = 0; mt < 4; ++mt)
#pragma unroll
        for (int nt = 0; nt < 4; ++nt)
#pragma unroll
            for (int e = 0; e < 4; ++e) acc[mt][nt][e] = 0.f;

    // per-thread cp.async coords: row = tid>>1 (0..127), seg = tid&1
    int ld_row = tid >> 1, ld_seg = tid & 1;
    int ld_sseg = ld_seg ^ ((ld_row >> 2) & 1);
    size_t g_off_base = (size_t)ld_row * DD + ld_seg * 8;
    uint32_t s_off = (uint32_t)(ld_row * 32 + ld_sseg * 16);

    // per-lane ldmatrix coords
    int amat = lane >> 3;
    int a_rin = (lane & 7) + ((amat & 1) << 3);
    int a_ksel = amat >> 1;
    int b_rin = lane & 7;
    int b_ksel = (lane >> 3) & 1;

    const int NCH = DD / 16;  // 32

    // prologue: stage 0
#pragma unroll
    for (int tl = 0; tl < 4; ++tl)
        cpasync16(sb + tl * TILE_BYTES + s_off, src[tl] + g_off_base);
    cpasync_commit();

    for (int i = 0; i < NCH; ++i) {
        cpasync_wait0();
        __syncthreads();
        if (i + 1 < NCH) {
            uint32_t stb = sb + ((i + 1) & 1) * (4 * TILE_BYTES);
            size_t go = g_off_base + (size_t)(i + 1) * 16;
#pragma unroll
            for (int tl = 0; tl < 4; ++tl)
                cpasync16(stb + tl * TILE_BYTES + s_off, src[tl] + go);
            cpasync_commit();
        }
        uint32_t cb = sb + (i & 1) * (4 * TILE_BYTES);

        uint32_t ah[4][4], al[4][4], bh[4][2], bl[4][2];
#pragma unroll
        for (int nt = 0; nt < 4; ++nt) {
            int n = warp_n * 32 + nt * 8 + b_rin;
            int sseg = b_ksel ^ ((n >> 2) & 1);
            uint32_t off = (uint32_t)(n * 32 + sseg * 16);
            ldsm_x2(bh[nt], cb + 2 * TILE_BYTES + off);
            ldsm_x2(bl[nt], cb + 3 * TILE_BYTES + off);
        }
#pragma unroll
        for (int mt = 0; mt < 4; ++mt) {
            int m = warp_m * 64 + mt * 16 + a_rin;
            int sseg = a_ksel ^ ((m >> 2) & 1);
            uint32_t off = (uint32_t)(m * 32 + sseg * 16);
            ldsm_x4(ah[mt], cb + off);
            ldsm_x4(al[mt], cb + TILE_BYTES + off);
        }
#pragma unroll
        for (int mt = 0; mt < 4; ++mt)
#pragma unroll
            for (int nt = 0; nt < 4; ++nt) {
                mma_bf16(acc[mt][nt], ah[mt], bh[nt]);
                mma_bf16(acc[mt][nt], al[mt], bh[nt]);
                mma_bf16(acc[mt][nt], ah[mt], bl[nt]);
            }
    }

    // epilogue: c-frag lane mapping r=lane/4, c=(lane%4)*2 (+8 rows for c2,c3)
    int er = lane >> 2, ec = (lane & 3) * 2;
#pragma unroll
    for (int mt = 0; mt < 4; ++mt) {
#pragma unroll
        for (int nt = 0; nt < 4; ++nt) {
            int row0 = rowBase + warp_m * 64 + mt * 16 + er;
            int col = colBase + warp_n * 32 + nt * 8 + ec;
            *(float2*)(out + (size_t)row0 * DD + col) = make_float2(acc[mt][nt][0], acc[mt][nt][1]);
            *(float2*)(out + (size_t)(row0 + 8) * DD + col) = make_float2(acc[mt][nt][2], acc[mt][nt][3]);
        }
    }
}

extern "C" void kernel_launch(void* const* d_in, const int* in_sizes, int n_in,
                              void* d_out, int out_size) {
    (void)in_sizes; (void)n_in; (void)out_size;
    const float* queries = (const float*)d_in[0];
    const float* keys    = (const float*)d_in[1];
    const float* values  = (const float*)d_in[2];
    const float* wq      = (const float*)d_in[3];
    const float* wk      = (const float*)d_in[4];
    const float* wv      = (const float*)d_in[5];
    const float* wo      = (const float*)d_in[6];
    float* out = (float*)d_out;

    // selection path
    k_qpart<<<dim3(BB, 2, 16), 256>>>(queries);
    k_rvec<<<BB, 512>>>(wq, wk);
    k_mc<<<dim3(LL / 8, BB), 256>>>(keys);
    k_topk<<<BB, 256>>>();

    // W = wv @ wo (fp32), then transpose+split to bf16 [N][K]
    k_gemm_w<<<dim3(DD / 32, DD / 32), 256>>>(wv, wo);
    k_wsplit<<<dim3(DD / 32, DD / 32), 256>>>();

    // blended values -> bf16 hi/lo, then tensor-core GEMM
    k_vagg<<<dim3(LL, BB), 128>>>(values);
    k_gemm_mma<<<dim3(DD / 128, (BB * LL) / 128), 256>>>(out);
}

// round 10
// speedup vs baseline: 2.4085x; 1.1468x over previous
#include <cuda_runtime.h>
#include <cuda_bf16.h>
#include <math.h>
#include <stdint.h>

#define BB 4
#define LL 2048
#define DD 512
#define KTOP 7
typedef unsigned long long ULL;

// ---------------- scratch (device globals; no allocation allowed) ----------
__device__ float g_part[BB * 16 * DD];
__device__ float g_qsp[BB * 16 * DD];   // partial qs (per c-chunk)
__device__ float g_r[BB * DD];
__device__ float g_mc[BB * LL];
__device__ float g_wt[BB * 8];
__device__ int   g_dl[BB * 8];
__device__ __nv_bfloat16 g_Ahi[(size_t)BB * LL * DD];
__device__ __nv_bfloat16 g_Alo[(size_t)BB * LL * DD];
__device__ __nv_bfloat16 g_Bhi[DD * DD];   // W transposed: [N][K] (col-major B)
__device__ __nv_bfloat16 g_Blo[DD * DD];

// ---------------- f32x2 helpers (for the small W GEMM) ----------------------
__device__ __forceinline__ ULL pack2(float x) {
    ULL r; unsigned u = __float_as_uint(x);
    asm("mov.b64 %0, {%1, %1};" : "=l"(r) : "r"(u));
    return r;
}
__device__ __forceinline__ void fma2(ULL& d, ULL a, ULL b) {
    asm("fma.rn.f32x2 %0, %1, %2, %0;" : "+l"(d) : "l"(a), "l"(b));
}
__device__ __forceinline__ float2 unpack2(ULL v) {
    float2 f;
    asm("mov.b64 {%0, %1}, %2;" : "=f"(f.x), "=f"(f.y) : "l"(v));
    return f;
}
__device__ __forceinline__ uint32_t smem_u32(const void* p) {
    uint32_t a;
    asm("{ .reg .u64 t; cvta.to.shared.u64 t, %1; cvt.u32.u64 %0, t; }" : "=r"(a) : "l"(p));
    return a;
}

// ---------------- mma.sync / cp.async helpers --------------------------------
__device__ __forceinline__ void ldsm_x4(uint32_t* d, uint32_t addr) {
    asm volatile("ldmatrix.sync.aligned.m8n8.x4.shared.b16 {%0,%1,%2,%3}, [%4];"
                 : "=r"(d[0]), "=r"(d[1]), "=r"(d[2]), "=r"(d[3]) : "r"(addr));
}
__device__ __forceinline__ void ldsm_x2(uint32_t* d, uint32_t addr) {
    asm volatile("ldmatrix.sync.aligned.m8n8.x2.shared.b16 {%0,%1}, [%2];"
                 : "=r"(d[0]), "=r"(d[1]) : "r"(addr));
}
__device__ __forceinline__ void mma_bf16(float* c, const uint32_t* a, const uint32_t* b) {
    asm volatile(
        "mma.sync.aligned.m16n8k16.row.col.f32.bf16.bf16.f32 "
        "{%0,%1,%2,%3}, {%4,%5,%6,%7}, {%8,%9}, {%0,%1,%2,%3};"
        : "+f"(c[0]), "+f"(c[1]), "+f"(c[2]), "+f"(c[3])
        : "r"(a[0]), "r"(a[1]), "r"(a[2]), "r"(a[3]), "r"(b[0]), "r"(b[1]));
}
__device__ __forceinline__ void cpasync16(uint32_t dst, const void* src) {
    asm volatile("cp.async.cg.shared.global [%0], [%1], 16;" :: "r"(dst), "l"(src));
}
__device__ __forceinline__ void cpasync_commit() {
    asm volatile("cp.async.commit_group;" ::: "memory");
}
__device__ __forceinline__ void cpasync_wait0() {
    asm volatile("cp.async.wait_group 0;" ::: "memory");
}

// ---------------- K1: partial column-sums of queries ------------------------
__global__ void k_qpart(const float* __restrict__ q) {
    int b = blockIdx.x, dchunk = blockIdx.y, ts = blockIdx.z;
    int d = dchunk * 256 + threadIdx.x;
    const float* base = q + (size_t)b * LL * DD + (size_t)(ts * 128) * DD + d;
    float s = 0.f;
#pragma unroll 8
    for (int t = 0; t < 128; ++t) s += base[(size_t)t * DD];
    g_part[(b * 16 + ts) * DD + d] = s;
}

// ---------------- K2a: partial qs over one 32-wide c-chunk ------------------
// grid (16, B), block 512: g_qsp[b][chunk][j] = sum_{c in chunk} qbar[c]*wq[c][j]
__global__ __launch_bounds__(512) void k_rv_a(const float* __restrict__ wq) {
    __shared__ float qbc[32];
    int chunk = blockIdx.x, b = blockIdx.y, tid = threadIdx.x;
    if (tid < 32) {
        int c = chunk * 32 + tid;
        float s = 0.f;
#pragma unroll
        for (int p = 0; p < 16; ++p) s += g_part[(b * 16 + p) * DD + c];
        qbc[tid] = s;
    }
    __syncthreads();
    float acc = 0.f;
    const float* wqr = wq + (size_t)(chunk * 32) * DD + tid;
#pragma unroll
    for (int j = 0; j < 32; ++j) acc += qbc[j] * wqr[(size_t)j * DD];
    g_qsp[(b * 16 + chunk) * DD + tid] = acc;
}

// ---------------- K2b: reduce qs, then r = wk @ qs * 1/16384 ----------------
// grid B, block 512
__global__ __launch_bounds__(512) void k_rv_b(const float* __restrict__ wk) {
    __shared__ float qs[DD];
    int b = blockIdx.x, tid = threadIdx.x;
    float s = 0.f;
#pragma unroll
    for (int ch = 0; ch < 16; ++ch) s += g_qsp[(b * 16 + ch) * DD + tid];
    qs[tid] = s;
    __syncthreads();
    const float4* wkr = (const float4*)(wk + (size_t)tid * DD);
    float r = 0.f;
#pragma unroll 4
    for (int d4 = 0; d4 < DD / 4; ++d4) {
        float4 v = wkr[d4];
        r += v.x * qs[d4 * 4] + v.y * qs[d4 * 4 + 1] + v.z * qs[d4 * 4 + 2] + v.w * qs[d4 * 4 + 3];
    }
    g_r[b * DD + tid] = r * (1.0f / (8.0f * 2048.0f));
}

// ---------------- K3: mean_corr[b,j] = keys[b,j,:] . r[b] -------------------
__global__ void k_mc(const float* __restrict__ keys) {
    __shared__ float rs[DD];
    int b = blockIdx.y, tid = threadIdx.x;
    rs[tid] = g_r[b * DD + tid];
    rs[tid + 256] = g_r[b * DD + tid + 256];
    __syncthreads();
    int warp = tid >> 5, lane = tid & 31;
    int j = blockIdx.x * 8 + warp;
    const float* kr = keys + ((size_t)b * LL + j) * DD;
    float acc = 0.f;
#pragma unroll
    for (int i = 0; i < 16; ++i) acc += kr[lane + 32 * i] * rs[lane + 32 * i];
#pragma unroll
    for (int o = 16; o; o >>= 1) acc += __shfl_down_sync(0xffffffffu, acc, o);
    if (lane == 0) g_mc[b * LL + j] = acc;
}

// ---------------- K4: top-7 + softmax, log-merge ----------------------------
__device__ __forceinline__ bool topgt(float a, int ia, float b, int ib) {
    return a > b || (a == b && ia < ib);  // lax.top_k tie-break: lower index
}
__global__ void k_topk() {
    int b = blockIdx.x, tid = threadIdx.x;
    __shared__ float sv[256][8];
    __shared__ int   si[256][8];
    float v[KTOP]; int ix[KTOP];
#pragma unroll
    for (int j = 0; j < KTOP; ++j) { v[j] = -INFINITY; ix[j] = 0x7fffffff; }
    const float* mc = g_mc + b * LL;
#pragma unroll
    for (int it = 0; it < LL / 256; ++it) {
        int i = tid + it * 256;
        float x = mc[i];
        if (topgt(x, i, v[KTOP - 1], ix[KTOP - 1])) {
            float cv = x; int ci = i;
#pragma unroll
            for (int j = 0; j < KTOP; ++j) {
                if (topgt(cv, ci, v[j], ix[j])) {
                    float tv = v[j]; int ti = ix[j];
                    v[j] = cv; ix[j] = ci;
                    cv = tv; ci = ti;
                }
            }
        }
    }
#pragma unroll
    for (int j = 0; j < KTOP; ++j) { sv[tid][j] = v[j]; si[tid][j] = ix[j]; }
    __syncthreads();
    for (int s = 128; s >= 1; s >>= 1) {
        if (tid < s) {
            float mv[KTOP]; int mi[KTOP];
            int p = 0, q = 0;
#pragma unroll
            for (int r = 0; r < KTOP; ++r) {
                float av = sv[tid][p], bv2 = sv[tid + s][q];
                int   ai = si[tid][p], bi2 = si[tid + s][q];
                if (topgt(av, ai, bv2, bi2)) { mv[r] = av; mi[r] = ai; ++p; }
                else                          { mv[r] = bv2; mi[r] = bi2; ++q; }
            }
#pragma unroll
            for (int r = 0; r < KTOP; ++r) { sv[tid][r] = mv[r]; si[tid][r] = mi[r]; }
        }
        __syncthreads();
    }
    if (tid == 0) {
        float m = sv[0][0];
        float e[KTOP], ssum = 0.f;
#pragma unroll
        for (int i = 0; i < KTOP; ++i) { e[i] = expf(sv[0][i] - m); ssum += e[i]; }
        float inv = 1.0f / ssum;
#pragma unroll
        for (int i = 0; i < KTOP; ++i) { g_wt[b * 8 + i] = e[i] * inv; g_dl[b * 8 + i] = si[0][i]; }
    }
}

// ---------------- W-GEMM + split: g_Bhi/g_Blo[n][k] = split((wv@wo)^T) ------
// 32x32 tiles, 256 blocks; epilogue stages the tile in smem and writes the
// bf16 hi/lo transposed (coalesced along K). No fp32 g_W roundtrip.
__global__ __launch_bounds__(256) void k_gemm_w(const float* __restrict__ wv,
                                                const float* __restrict__ wo) {
    __shared__ float As[32][36];
    __shared__ float Bs[32][32];
    __shared__ float Cs[32][33];
    int tid = threadIdx.x;
    int tx = tid & 15, ty = tid >> 4;
    int rowBase = blockIdx.y * 32, colBase = blockIdx.x * 32;
    ULL acc0 = 0ull, acc1 = 0ull;
    for (int k0 = 0; k0 < DD; k0 += 32) {
        {
            int r = tid >> 3;
            int c4 = (tid & 7) * 4;
            float4 v = *(const float4*)(wv + (size_t)(rowBase + r) * DD + k0 + c4);
            As[c4][r] = v.x; As[c4 + 1][r] = v.y; As[c4 + 2][r] = v.z; As[c4 + 3][r] = v.w;
            float4 w = *(const float4*)(wo + (size_t)(k0 + r) * DD + colBase + c4);
            *(float4*)&Bs[r][c4] = w;
        }
        __syncthreads();
#pragma unroll 8
        for (int k = 0; k < 32; ++k) {
            ULL a0 = pack2(As[k][ty * 2]);
            ULL a1 = pack2(As[k][ty * 2 + 1]);
            ULL b = *(const ULL*)&Bs[k][tx * 2];
            fma2(acc0, a0, b);
            fma2(acc1, a1, b);
        }
        __syncthreads();
    }
    float2 c0 = unpack2(acc0);
    float2 c1 = unpack2(acc1);
    Cs[ty * 2][tx * 2] = c0.x;     Cs[ty * 2][tx * 2 + 1] = c0.y;
    Cs[ty * 2 + 1][tx * 2] = c1.x; Cs[ty * 2 + 1][tx * 2 + 1] = c1.y;
    __syncthreads();
#pragma unroll
    for (int i = 0; i < 4; ++i) {
        int idx = tid + i * 256;
        int n = idx >> 5, m = idx & 31;      // m = K index (W row), n = N index
        float x = Cs[m][n];
        __nv_bfloat16 h = __float2bfloat16(x);
        __nv_bfloat16 l = __float2bfloat16(x - __bfloat162float(h));
        size_t dst = (size_t)(colBase + n) * DD + rowBase + m;
        g_Bhi[dst] = h;
        g_Blo[dst] = l;
    }
}

// ---------------- K6: Vagg blended values -> bf16 hi/lo A -------------------
__global__ void k_vagg(const float* __restrict__ values) {
    int t = blockIdx.x, b = blockIdx.y;
    __shared__ float w[KTOP];
    __shared__ int dl[KTOP];
    if (threadIdx.x < KTOP) { w[threadIdx.x] = g_wt[b * 8 + threadIdx.x]; dl[threadIdx.x] = g_dl[b * 8 + threadIdx.x]; }
    __syncthreads();
    int d4 = threadIdx.x;
    float4 acc = make_float4(0.f, 0.f, 0.f, 0.f);
#pragma unroll
    for (int k = 0; k < KTOP; ++k) {
        int src = (t + dl[k]) & (LL - 1);
        const float4* row = (const float4*)(values + ((size_t)b * LL + src) * DD);
        float4 v = row[d4];
        float wk = w[k];
        acc.x += wk * v.x; acc.y += wk * v.y; acc.z += wk * v.z; acc.w += wk * v.w;
    }
    size_t base = ((size_t)b * LL + t) * DD + d4 * 4;
    float a[4] = {acc.x, acc.y, acc.z, acc.w};
    __nv_bfloat16 h[4], l[4];
#pragma unroll
    for (int j = 0; j < 4; ++j) {
        h[j] = __float2bfloat16(a[j]);
        l[j] = __float2bfloat16(a[j] - __bfloat162float(h[j]));
    }
    *(__nv_bfloat162*)(g_Ahi + base)     = __nv_bfloat162(h[0], h[1]);
    *(__nv_bfloat162*)(g_Ahi + base + 2) = __nv_bfloat162(h[2], h[3]);
    *(__nv_bfloat162*)(g_Alo + base)     = __nv_bfloat162(l[0], l[1]);
    *(__nv_bfloat162*)(g_Alo + base + 2) = __nv_bfloat162(l[2], l[3]);
}

// ---------------- main GEMM: mma.sync bf16-split, cp.async 2-stage pipeline -
#define TILE_BYTES 4096
__global__ __launch_bounds__(256) void k_gemm_mma(float* __restrict__ out) {
    __shared__ char smem_raw[2 * 4 * TILE_BYTES];
    int tid = threadIdx.x;
    int wid = tid >> 5, lane = tid & 31;
    int warp_m = wid & 1, warp_n = wid >> 1;
    int rowBase = blockIdx.y * 128, colBase = blockIdx.x * 128;

    const __nv_bfloat16* src[4] = {
        g_Ahi + (size_t)rowBase * DD,
        g_Alo + (size_t)rowBase * DD,
        g_Bhi + (size_t)colBase * DD,
        g_Blo + (size_t)colBase * DD };

    uint32_t sb = smem_u32(smem_raw);

    float acc[4][4][4];
#pragma unroll
    for (int mt = 0; mt < 4; ++mt)
#pragma unroll
        for (int nt = 0; nt < 4; ++nt)
#pragma unroll
            for (int e = 0; e < 4; ++e) acc[mt][nt][e] = 0.f;

    int ld_row = tid >> 1, ld_seg = tid & 1;
    int ld_sseg = ld_seg ^ ((ld_row >> 2) & 1);
    size_t g_off_base = (size_t)ld_row * DD + ld_seg * 8;
    uint32_t s_off = (uint32_t)(ld_row * 32 + ld_sseg * 16);

    int amat = lane >> 3;
    int a_rin = (lane & 7) + ((amat & 1) << 3);
    int a_ksel = amat >> 1;
    int b_rin = lane & 7;
    int b_ksel = (lane >> 3) & 1;

    const int NCH = DD / 16;  // 32

#pragma unroll
    for (int tl = 0; tl < 4; ++tl)
        cpasync16(sb + tl * TILE_BYTES + s_off, src[tl] + g_off_base);
    cpasync_commit();

    for (int i = 0; i < NCH; ++i) {
        cpasync_wait0();
        __syncthreads();
        if (i + 1 < NCH) {
            uint32_t stb = sb + ((i + 1) & 1) * (4 * TILE_BYTES);
            size_t go = g_off_base + (size_t)(i + 1) * 16;
#pragma unroll
            for (int tl = 0; tl < 4; ++tl)
                cpasync16(stb + tl * TILE_BYTES + s_off, src[tl] + go);
            cpasync_commit();
        }
        uint32_t cb = sb + (i & 1) * (4 * TILE_BYTES);

        uint32_t ah[4][4], al[4][4], bh[4][2], bl[4][2];
#pragma unroll
        for (int nt = 0; nt < 4; ++nt) {
            int n = warp_n * 32 + nt * 8 + b_rin;
            int sseg = b_ksel ^ ((n >> 2) & 1);
            uint32_t off = (uint32_t)(n * 32 + sseg * 16);
            ldsm_x2(bh[nt], cb + 2 * TILE_BYTES + off);
            ldsm_x2(bl[nt], cb + 3 * TILE_BYTES + off);
        }
#pragma unroll
        for (int mt = 0; mt < 4; ++mt) {
            int m = warp_m * 64 + mt * 16 + a_rin;
            int sseg = a_ksel ^ ((m >> 2) & 1);
            uint32_t off = (uint32_t)(m * 32 + sseg * 16);
            ldsm_x4(ah[mt], cb + off);
            ldsm_x4(al[mt], cb + TILE_BYTES + off);
        }
#pragma unroll
        for (int mt = 0; mt < 4; ++mt)
#pragma unroll
            for (int nt = 0; nt < 4; ++nt) {
                mma_bf16(acc[mt][nt], ah[mt], bh[nt]);
                mma_bf16(acc[mt][nt], al[mt], bh[nt]);
                mma_bf16(acc[mt][nt], ah[mt], bl[nt]);
            }
    }

    int er = lane >> 2, ec = (lane & 3) * 2;
#pragma unroll
    for (int mt = 0; mt < 4; ++mt) {
#pragma unroll
        for (int nt = 0; nt < 4; ++nt) {
            int row0 = rowBase + warp_m * 64 + mt * 16 + er;
            int col = colBase + warp_n * 32 + nt * 8 + ec;
            *(float2*)(out + (size_t)row0 * DD + col) = make_float2(acc[mt][nt][0], acc[mt][nt][1]);
            *(float2*)(out + (size_t)(row0 + 8) * DD + col) = make_float2(acc[mt][nt][2], acc[mt][nt][3]);
        }
    }
}

extern "C" void kernel_launch(void* const* d_in, const int* in_sizes, int n_in,
                              void* d_out, int out_size) {
    (void)in_sizes; (void)n_in; (void)out_size;
    const float* queries = (const float*)d_in[0];
    const float* keys    = (const float*)d_in[1];
    const float* values  = (const float*)d_in[2];
    const float* wq      = (const float*)d_in[3];
    const float* wk      = (const float*)d_in[4];
    const float* wv      = (const float*)d_in[5];
    const float* wo      = (const float*)d_in[6];
    float* out = (float*)d_out;

    // selection path
    k_qpart<<<dim3(BB, 2, 16), 256>>>(queries);
    k_rv_a<<<dim3(16, BB), 512>>>(wq);
    k_rv_b<<<BB, 512>>>(wk);
    k_mc<<<dim3(LL / 8, BB), 256>>>(keys);
    k_topk<<<BB, 256>>>();

    // W = wv @ wo, split+transpose fused into epilogue
    k_gemm_w<<<dim3(DD / 32, DD / 32), 256>>>(wv, wo);

    // blended values -> bf16 hi/lo, then tensor-core GEMM
    k_vagg<<<dim3(LL, BB), 128>>>(values);
    k_gemm_mma<<<dim3(DD / 128, (BB * LL) / 128), 256>>>(out);
}